// round 6
// baseline (speedup 1.0000x reference)
#include <cuda_runtime.h>
#include <math.h>

// ---------------- static config ----------------
static constexpr int NB = 8;
static constexpr int ND = 256;
static constexpr int NC = 64;
static constexpr int NHID = 128;
static constexpr int NS = 64;
static constexpr int NHH = 28, NWW = 28;
static constexpr int NL = NHH * NWW;      // 784
static constexpr int NHEAD = 16;
static constexpr int NPAIRS = NB * NL / 2;  // 3136
static constexpr int PPB = NL / 2;          // 392

// ---------------- scratch arena ----------------
static constexpr long O_X1O   = 0;                          // (8,64,784)
static constexpr long O_T2    = O_X1O   + (long)NB*NC*NL;   // (8,128,784)
static constexpr long O_TMP1  = O_T2    + (long)NB*NHID*NL; // (8,64,784)
static constexpr long O_BCDT0 = O_TMP1  + (long)NB*NC*NL;   // (8,192,784)
static constexpr long O_H     = O_BCDT0 + (long)NB*192*NL;  // (8,64,64)
static constexpr long O_H2    = O_H     + (long)NB*NC*NS;   // (8,64,64)
static constexpr long O_QKV   = O_H2    + (long)NB*NC*NS;   // (8,192,784)
static constexpr long O_O     = O_QKV   + (long)NB*192*NL;  // (8,64,784)
static constexpr long O_XA    = O_O     + (long)NB*NC*NL;   // (8,256,784)
static constexpr long O_M1    = O_XA    + (long)NB*ND*NL;   // (8,128,784)
static constexpr long SCR_TOTAL = O_M1 + (long)NB*NHID*NL;

__device__ __align__(16) float g_scr[SCR_TOTAL];

enum { M_NONE = 0, M_ADD_BN, M_BN_RELU, M_BN_ADD, M_BN };

// ---------------- pointwise conv, pixel-pair tiled ----------------
template <int CIN>
__global__ void pwconv_k(const float* __restrict__ in, long ibs,
                         const float* __restrict__ w, int cout,
                         const float* __restrict__ bias,
                         const float* __restrict__ bnp,
                         const float* __restrict__ res, long rbs,
                         float* __restrict__ out, long obs, int mode) {
    constexpr int OT = 16;
    __shared__ float ws[CIN * OT];
    int obase = blockIdx.x * OT;
    for (int idx = threadIdx.x; idx < CIN * OT; idx += 128) {
        int c = idx >> 4, i = idx & 15;
        ws[idx] = w[(long)(obase + i) * CIN + c];
    }
    __syncthreads();
    int pp = blockIdx.y * 128 + threadIdx.x;
    if (pp >= NPAIRS) return;
    int b = pp / PPB;
    int l = (pp % PPB) * 2;
    const float2* ip2 = reinterpret_cast<const float2*>(in + (long)b * ibs + l);

    float a0[OT], a1[OT];
#pragma unroll
    for (int i = 0; i < OT; i++) { a0[i] = 0.f; a1[i] = 0.f; }
#pragma unroll 4
    for (int c = 0; c < CIN; c++) {
        float2 xv = ip2[c * (NL / 2)];
        const float* wc = ws + c * OT;
#pragma unroll
        for (int i = 0; i < OT; i++) {
            float wv = wc[i];
            a0[i] += wv * xv.x;
            a1[i] += wv * xv.y;
        }
    }
#pragma unroll
    for (int i = 0; i < OT; i++) {
        int o = obase + i;
        float s0 = a0[i], s1 = a1[i];
        if (bias) { s0 += bias[o]; s1 += bias[o]; }
        if (mode >= M_ADD_BN) {
            long roff = (long)b * rbs + (long)o * NL + l;
            if (mode == M_ADD_BN) {
                float2 rv = *reinterpret_cast<const float2*>(res + roff);
                s0 += rv.x; s1 += rv.y;
            }
            float g = bnp[o], be = bnp[cout + o], mm = bnp[2 * cout + o], vv = bnp[3 * cout + o];
            float sc = g * rsqrtf(vv + 1e-5f);
            s0 = (s0 - mm) * sc + be;
            s1 = (s1 - mm) * sc + be;
            if (mode == M_BN_RELU) { s0 = fmaxf(s0, 0.f); s1 = fmaxf(s1, 0.f); }
            if (mode == M_BN_ADD) {
                float2 rv = *reinterpret_cast<const float2*>(res + roff);
                s0 += rv.x; s1 += rv.y;
            }
        }
        *reinterpret_cast<float2*>(out + (long)b * obs + (long)o * NL + l) =
            make_float2(s0, s1);
    }
}

// ---------------- fused star MLP ----------------
__global__ void star_k(const float* __restrict__ in,
                       const float* __restrict__ w1, const float* __restrict__ b1,
                       const float* __restrict__ w2, const float* __restrict__ b2,
                       float* __restrict__ out) {
    constexpr int OT = 16, CIN = NC;
    __shared__ float ws1[CIN * OT], ws2[CIN * OT];
    int obase = blockIdx.x * OT;
    for (int idx = threadIdx.x; idx < CIN * OT; idx += 128) {
        int c = idx >> 4, i = idx & 15;
        ws1[idx] = w1[(long)(obase + i) * CIN + c];
        ws2[idx] = w2[(long)(obase + i) * CIN + c];
    }
    __syncthreads();
    int pp = blockIdx.y * 128 + threadIdx.x;
    if (pp >= NPAIRS) return;
    int b = pp / PPB;
    int l = (pp % PPB) * 2;
    const float2* ip2 = reinterpret_cast<const float2*>(in + (long)b * NC * NL + l);

    float p0[OT], p1[OT], q0[OT], q1[OT];
#pragma unroll
    for (int i = 0; i < OT; i++) { p0[i] = p1[i] = q0[i] = q1[i] = 0.f; }
#pragma unroll 4
    for (int c = 0; c < CIN; c++) {
        float2 xv = ip2[c * (NL / 2)];
        const float* w1c = ws1 + c * OT;
        const float* w2c = ws2 + c * OT;
#pragma unroll
        for (int i = 0; i < OT; i++) {
            p0[i] += w1c[i] * xv.x; p1[i] += w1c[i] * xv.y;
            q0[i] += w2c[i] * xv.x; q1[i] += w2c[i] * xv.y;
        }
    }
#pragma unroll
    for (int i = 0; i < OT; i++) {
        int o = obase + i;
        float h0 = fminf(fmaxf(p0[i] + b1[o], 0.f), 6.f);
        float h1 = fminf(fmaxf(p1[i] + b1[o], 0.f), 6.f);
        float s0 = h0 * (q0[i] + b2[o]);
        float s1 = h1 * (q1[i] + b2[o]);
        *reinterpret_cast<float2*>(out + ((long)b * NHID + o) * NL + l) =
            make_float2(s0, s1);
    }
}

// ---------------- depthwise 7x7: 2 px/thread ----------------
__global__ void dw7x7_k(const float* __restrict__ in, long ibs,
                        const float* __restrict__ w, const float* __restrict__ bias,
                        const float* __restrict__ bnp,
                        float* __restrict__ out, long obs) {
    int bc = blockIdx.x;
    int c = bc % NC, b = bc / NC;
    const float* ip = in + (long)b * ibs + (long)c * NL;
    __shared__ float pl[34 * 34];
    __shared__ float wsh[49];
    int t = threadIdx.x;  // 392
    for (int i = t; i < 34 * 34; i += 392) pl[i] = 0.f;
    if (t < 49) wsh[t] = w[c * 49 + t];
    __syncthreads();
    {
        int l = t * 2;
        int y = l / NWW, x = l % NWW;
        float2 v = *reinterpret_cast<const float2*>(ip + l);
        pl[(y + 3) * 34 + x + 3] = v.x;
        pl[(y + 3) * 34 + x + 4] = v.y;
    }
    __syncthreads();
    float sc = 1.f, sh = 0.f;
    if (bnp) {
        float g = bnp[c], be = bnp[NC + c], mm = bnp[2 * NC + c], vv = bnp[3 * NC + c];
        sc = g * rsqrtf(vv + 1e-5f);
        sh = be - mm * sc;
    }
    float bi = bias[c];
    int y = t / 14, x0 = (t % 14) * 2;
    float s0 = 0.f, s1 = 0.f;
#pragma unroll
    for (int ky = 0; ky < 7; ky++) {
        float r[8];
        const float* row = pl + (y + ky) * 34 + x0;
#pragma unroll
        for (int kx = 0; kx < 8; kx++) r[kx] = row[kx];
#pragma unroll
        for (int kx = 0; kx < 7; kx++) {
            float wv = wsh[ky * 7 + kx];
            s0 += wv * r[kx];
            s1 += wv * r[kx + 1];
        }
    }
    s0 = (s0 + bi) * sc + sh;
    s1 = (s1 + bi) * sc + sh;
    *reinterpret_cast<float2*>(out + (long)b * obs + (long)c * NL + y * NWW + x0) =
        make_float2(s0, s1);
}

// ---------------- branch 2 fully fused ----------------
__global__ void mra_branch_k(const float* __restrict__ x,
                             const float* __restrict__ h1w, const float* __restrict__ v1w,
                             const float* __restrict__ h2w, const float* __restrict__ v2w,
                             const float* __restrict__ bnp, float* __restrict__ xa) {
    int bc = blockIdx.x;
    int c = bc % NC, b = bc / NC;
    const float* ip = x + ((long)b * ND + NC + c) * NL;
    __shared__ float xp[NL], mp[NL];
    __shared__ float xs[100], ht[190], vt[190], c2[190], c2v[190], att_s[100];
    int t = threadIdx.x;  // 196
    for (int i = t; i < NL; i += 196) xp[i] = ip[i];
    __syncthreads();
    for (int i = t; i < NL; i += 196) {
        int y = i / NWW, xx = i % NWW;
        float mx = -1e30f;
        for (int dy = -1; dy <= 1; dy++) {
            int yy = y + dy;
            if (yy < 0 || yy >= NHH) continue;
            for (int dx = -1; dx <= 1; dx++) {
                int xxx = xx + dx;
                if (xxx < 0 || xxx >= NWW) continue;
                mx = fmaxf(mx, xp[yy * NWW + xxx]);
            }
        }
        mp[i] = mx;
    }
    __syncthreads();
    if (t < 100) {
        int i = t / 10, j = t % 10;
        const float filt[4] = {1.f, 3.f, 3.f, 1.f};
        float s = 0.f;
        for (int fy = 0; fy < 4; fy++) {
            int oy = 3 * i + fy - 1;
            if (oy < 0) oy = -oy;
            if (oy >= NHH) oy = 2 * NHH - 2 - oy;
            for (int fx = 0; fx < 4; fx++) {
                int ox = 3 * j + fx - 1;
                if (ox < 0) ox = -ox;
                if (ox >= NWW) ox = 2 * NWW - 2 - ox;
                s += filt[fy] * filt[fx] * mp[oy * NWW + ox];
            }
        }
        xs[t] = s * (1.f / 64.f);
    }
    __syncthreads();
    if (t < 190) {
        {
            int row = t / 20, col = t % 20;
            ht[t] = (col < 10) ? xs[row * 10 + col] : 0.f;
        }
        {
            int a = t / 10, b2 = t % 10;
            int k = b2 * 19 + a, row = k / 20, col = k % 20;
            vt[t] = (col < 10) ? xs[col * 10 + row] : 0.f;
        }
    }
    __syncthreads();
    if (t < 190) {
        {
            int r = t / 19, j = t % 19;
            float s = 0.f;
            for (int ky = 0; ky < 11; ky++) {
                int yy = r + ky - 5;
                if (yy < 0 || yy >= 10) continue;
                for (int kx = 0; kx < 3; kx++) {
                    int xx = j + kx - 1;
                    if (xx < 0 || xx >= 19) continue;
                    s += h2w[c * 33 + ky * 3 + kx] * ht[yy * 19 + xx];
                }
            }
            c2[t] = s;
        }
        {
            int y = t / 10, x2 = t % 10;
            float s = 0.f;
            for (int ky = 0; ky < 3; ky++) {
                int yy = y + ky - 1;
                if (yy < 0 || yy >= 19) continue;
                for (int kx = 0; kx < 11; kx++) {
                    int xx = x2 + kx - 5;
                    if (xx < 0 || xx >= 10) continue;
                    s += v2w[c * 33 + ky * 11 + kx] * vt[yy * 10 + xx];
                }
            }
            c2v[t] = s;
        }
    }
    __syncthreads();
    if (t < 100) {
        int y = t / 10, xx = t % 10;
        float s = 0.f;
        for (int ky = 0; ky < 11; ky++) {
            int yy = y + ky - 5;
            if (yy < 0 || yy >= 10) continue;
            for (int kx = 0; kx < 3; kx++) {
                int xxx = xx + kx - 1;
                if (xxx < 0 || xxx >= 10) continue;
                s += h1w[c * 33 + ky * 3 + kx] * xs[yy * 10 + xxx];
            }
        }
        for (int ky = 0; ky < 3; ky++) {
            int yy = y + ky - 1;
            if (yy < 0 || yy >= 10) continue;
            for (int kx = 0; kx < 11; kx++) {
                int xxx = xx + kx - 5;
                if (xxx < 0 || xxx >= 10) continue;
                s += v1w[c * 33 + ky * 11 + kx] * xs[yy * 10 + xxx];
            }
        }
        s += c2[y * 20 + xx];
        int k4 = xx * 20 + y;
        s += c2v[(k4 % 19) * 10 + (k4 / 19)];
        float g = bnp[c], be = bnp[NC + c], mm = bnp[2 * NC + c], vv = bnp[3 * NC + c];
        float sc = g * rsqrtf(vv + 1e-5f);
        s = (s - mm) * sc + be;
        att_s[t] = 1.f / (1.f + __expf(-s));
    }
    __syncthreads();
    float* op = xa + (long)b * ND * NL + (long)(NC + c) * NL;
    for (int i = t; i < NL; i += 196) {
        int y = i / NWW, xx = i % NWW;
        int yo = (y * 10) / NHH, xo = (xx * 10) / NWW;
        op[i] = xp[i] * att_s[yo * 10 + xo];
    }
}

// ---------------- SSD fused: dw3x3(dt,Bm) + softmax + h-GEMM ----------------
// grid (8 stile, NB), 256 threads, dynamic smem
__global__ void ssd_Wh_k(const float* __restrict__ x, const float* __restrict__ bcdt0,
                         const float* __restrict__ dw, const float* __restrict__ A_param,
                         float* __restrict__ h) {
    extern __shared__ float sm[];
    float* planes = sm;                 // 16 planes padded 30x30
    float* Wsh = sm + 16 * 900;         // 8 x 784
    int stile = blockIdx.x, b = blockIdx.y;
    int t = threadIdx.x;
    for (int i = t; i < 16 * 900; i += 256) planes[i] = 0.f;
    __syncthreads();
    for (int i = t; i < 16 * NL; i += 256) {
        int p = i / NL, l = i % NL;
        int ch = (p < 8) ? (stile * 8 + p) : (128 + stile * 8 + (p - 8));
        int y = l / NWW, xcol = l % NWW;
        planes[p * 900 + (y + 1) * 30 + xcol + 1] =
            bcdt0[((long)b * 192 + ch) * NL + l];
    }
    __syncthreads();
    int warp = t / 32, lane = t % 32;
    {
        int s = stile * 8 + warp;
        float wd[9], wb[9];
#pragma unroll
        for (int k = 0; k < 9; k++) {
            wd[k] = dw[(128 + s) * 9 + k];
            wb[k] = dw[s * 9 + k];
        }
        const float* dpl = planes + (8 + warp) * 900;
        const float* bpl = planes + warp * 900;
        float ap = A_param[s];
        float mx = -1e30f;
        for (int l = lane; l < NL; l += 32) {
            int y = l / NWW, xx = l % NWW;
            float v = 0.f;
#pragma unroll
            for (int ky = 0; ky < 3; ky++)
#pragma unroll
                for (int kx = 0; kx < 3; kx++)
                    v += wd[ky * 3 + kx] * dpl[(y + ky) * 30 + xx + kx];
            v += ap;
            Wsh[warp * NL + l] = v;
            mx = fmaxf(mx, v);
        }
#pragma unroll
        for (int o = 16; o > 0; o >>= 1) mx = fmaxf(mx, __shfl_xor_sync(0xffffffff, mx, o));
        float sum = 0.f;
        for (int l = lane; l < NL; l += 32) {
            float e = __expf(Wsh[warp * NL + l] - mx);
            Wsh[warp * NL + l] = e;
            sum += e;
        }
#pragma unroll
        for (int o = 16; o > 0; o >>= 1) sum += __shfl_xor_sync(0xffffffff, sum, o);
        float inv = 1.f / sum;
        for (int l = lane; l < NL; l += 32) {
            int y = l / NWW, xx = l % NWW;
            float v = 0.f;
#pragma unroll
            for (int ky = 0; ky < 3; ky++)
#pragma unroll
                for (int kx = 0; kx < 3; kx++)
                    v += wb[ky * 3 + kx] * bpl[(y + ky) * 30 + xx + kx];
            Wsh[warp * NL + l] *= inv * v;
        }
    }
    __syncthreads();
    // h phase: 8 warps, each 8 channels
    for (int i = 0; i < 8; i++) {
        int c = i * 8 + warp;
        const float* xsrc = x + ((long)b * ND + 128 + c) * NL;
        float acc[8];
#pragma unroll
        for (int k = 0; k < 8; k++) acc[k] = 0.f;
        for (int l = lane; l < NL; l += 32) {
            float xv = xsrc[l];
#pragma unroll
            for (int k = 0; k < 8; k++) acc[k] += xv * Wsh[k * NL + l];
        }
#pragma unroll
        for (int k = 0; k < 8; k++) {
#pragma unroll
            for (int o = 16; o > 0; o >>= 1)
                acc[k] += __shfl_down_sync(0xffffffff, acc[k], o);
        }
        if (lane == 0) {
#pragma unroll
            for (int k = 0; k < 8; k++)
                h[((long)b * NC + c) * NS + stile * 8 + k] = acc[k];
        }
    }
}

// ---------------- SSD mix fused (hz + gate + out proj) ----------------
// grid NB, 256 threads, dynamic smem: hs, us, wa, wb (4 x 4096 floats)
__global__ void ssd_mix_k(const float* __restrict__ h, const float* __restrict__ hzw,
                          const float* __restrict__ ow, const float* __restrict__ D,
                          float* __restrict__ h2) {
    extern __shared__ float sm[];
    float* hs = sm;
    float* us = sm + 4096;
    float* wa = sm + 2 * 4096;
    float* wb = sm + 3 * 4096;
    int b = blockIdx.x, t = threadIdx.x;
    for (int i = t; i < NC * NS; i += 256) hs[i] = h[(long)b * NC * NS + i];
    for (int i = t; i < NC * NC; i += 256) {
        wa[i] = hzw[i];
        wb[i] = hzw[NC * NC + i];
    }
    __syncthreads();
    float Dv = D[0];
    for (int idx = t; idx < NC * NS; idx += 256) {
        int o = idx >> 6, s = idx & 63;
        float s1 = 0.f, s2 = 0.f;
#pragma unroll 4
        for (int c = 0; c < NC; c++) {
            float hv = hs[c * NS + s];
            s1 += wa[o * NC + c] * hv;
            s2 += wb[o * NC + c] * hv;
        }
        float sil = s2 / (1.f + __expf(-s2));
        us[idx] = s1 * sil + s1 * Dv;
    }
    __syncthreads();
    for (int i = t; i < NC * NC; i += 256) wa[i] = ow[i];
    __syncthreads();
    for (int idx = t; idx < NC * NS; idx += 256) {
        int o = idx >> 6, s = idx & 63;
        float acc = 0.f;
#pragma unroll 4
        for (int c = 0; c < NC; c++) acc += wa[o * NC + c] * us[c * NS + s];
        h2[(long)b * NC * NS + idx] = acc;
    }
}

// ---------------- SSD out: x3 = h2 @ conv3x3(Cm), inline conv ----------------
// grid (4 cg, 4 lt, NB), 196 threads, dynamic smem
__global__ void ssd_out_k(const float* __restrict__ h2, const float* __restrict__ bcdt0,
                          const float* __restrict__ dw, float* __restrict__ xa) {
    extern __shared__ float sm[];
    float* inbuf = sm;             // 64 planes x 9 rows x 30 cols
    float* hst = sm + 64 * 270;    // 64 x 16 (transposed)
    float* wsh = hst + 1024;       // 64 x 9
    int cg = blockIdx.x, lt = blockIdx.y, b = blockIdx.z;
    int t = threadIdx.x;  // 196
    int r0 = lt * 7;
    for (int i = t; i < 64 * 270; i += 196) inbuf[i] = 0.f;
    for (int i = t; i < 64 * 9; i += 196) wsh[i] = dw[(64 + i / 9) * 9 + i % 9];
    for (int i = t; i < 16 * NS; i += 196) {
        int s = i / 16, ii = i % 16;
        hst[i] = h2[((long)b * NC + cg * 16 + ii) * NS + s];
    }
    __syncthreads();
    for (int i = t; i < 64 * 9 * 28; i += 196) {
        int s = i / 252, rem = i % 252;
        int rloc = rem / 28, col = rem % 28;
        int rr = r0 + rloc - 1;
        if (rr >= 0 && rr < NHH)
            inbuf[s * 270 + rloc * 30 + col + 1] =
                bcdt0[((long)b * 192 + 64 + s) * NL + rr * NWW + col];
    }
    __syncthreads();
    int l = lt * 196 + t;
    int ly = t / 28, xx = t % 28;
    float acc[16];
#pragma unroll
    for (int i = 0; i < 16; i++) acc[i] = 0.f;
    for (int s = 0; s < 64; s++) {
        const float* pb = inbuf + s * 270 + ly * 30 + xx;
        const float* wp = wsh + s * 9;
        float cv = 0.f;
#pragma unroll
        for (int ky = 0; ky < 3; ky++)
#pragma unroll
            for (int kx = 0; kx < 3; kx++)
                cv += wp[ky * 3 + kx] * pb[ky * 30 + kx];
        const float* hp = hst + s * 16;
#pragma unroll
        for (int i = 0; i < 16; i++) acc[i] += hp[i] * cv;
    }
#pragma unroll
    for (int i = 0; i < 16; i++)
        xa[(long)b * ND * NL + (long)(128 + cg * 16 + i) * NL + l] = acc[i];
}

// ---------------- GA attention ----------------
__global__ void attn_k(const float* __restrict__ qkv, float* __restrict__ o) {
    int blk = blockIdx.x;
    int rc = blk % 7;
    int bh = blk / 7;
    int head = bh % NHEAD, b = bh / NHEAD;
    __shared__ float Ks[NL * 4], Vs[NL * 4];
    const float* kbase = qkv + ((long)b * 192 + 64 + head * 4) * NL;
    const float* vbase = qkv + ((long)b * 192 + 128 + head * 4) * NL;
    for (int i = threadIdx.x; i < NL * 4; i += blockDim.x) {
        int d = i / NL, l = i % NL;
        Ks[l * 4 + d] = kbase[i];
        Vs[l * 4 + d] = vbase[i];
    }
    __syncthreads();
    int row = rc * 128 + threadIdx.x;
    if (row >= NL) return;
    const float* qb = qkv + ((long)b * 192 + head * 4) * NL;
    float q0 = qb[row] * 0.5f, q1 = qb[NL + row] * 0.5f;
    float q2 = qb[2 * NL + row] * 0.5f, q3 = qb[3 * NL + row] * 0.5f;
    float se = 0.f, a0 = 0.f, a1 = 0.f, a2 = 0.f, a3 = 0.f;
    const float4* K4 = reinterpret_cast<const float4*>(Ks);
    const float4* V4 = reinterpret_cast<const float4*>(Vs);
    for (int l = 0; l < NL; l++) {
        float4 kv = K4[l];
        float s = q0 * kv.x + q1 * kv.y + q2 * kv.z + q3 * kv.w;
        float p = __expf(s);
        float4 vv = V4[l];
        se += p;
        a0 += p * vv.x; a1 += p * vv.y; a2 += p * vv.z; a3 += p * vv.w;
    }
    float inv = 1.f / se;
    float* ob = o + ((long)b * NC + head * 4) * NL;
    ob[row] = a0 * inv;
    ob[NL + row] = a1 * inv;
    ob[2 * NL + row] = a2 * inv;
    ob[3 * NL + row] = a3 * inv;
}

// ---------------- launch ----------------
static constexpr int SMEM_WH  = (16 * 900 + 8 * NL) * 4;          // 82,688 B
static constexpr int SMEM_MIX = 4 * 4096 * 4;                     // 65,536 B
static constexpr int SMEM_OUT = (64 * 270 + 1024 + 576) * 4;      // 75,520 B

extern "C" void kernel_launch(void* const* d_in, const int* in_sizes, int n_in,
                              void* d_out, int out_size) {
    const float* x       = (const float*)d_in[0];
    const float* dw1_w   = (const float*)d_in[1];
    const float* dw1_b   = (const float*)d_in[2];
    const float* bn_dw1  = (const float*)d_in[3];
    const float* f1_w    = (const float*)d_in[4];
    const float* f1_b    = (const float*)d_in[5];
    const float* f2_w    = (const float*)d_in[6];
    const float* f2_b    = (const float*)d_in[7];
    const float* g_w     = (const float*)d_in[8];
    const float* g_b     = (const float*)d_in[9];
    const float* bn_g    = (const float*)d_in[10];
    const float* dw2_w   = (const float*)d_in[11];
    const float* dw2_b   = (const float*)d_in[12];
    const float* hatt1_w = (const float*)d_in[13];
    const float* vatt1_w = (const float*)d_in[14];
    const float* hatt2_w = (const float*)d_in[15];
    const float* vatt2_w = (const float*)d_in[16];
    const float* bn_mra  = (const float*)d_in[17];
    const float* bcdt_w  = (const float*)d_in[18];
    const float* ssd_dw  = (const float*)d_in[19];
    const float* hz_w    = (const float*)d_in[20];
    const float* out_w   = (const float*)d_in[21];
    const float* A_param = (const float*)d_in[22];
    const float* D_param = (const float*)d_in[23];
    const float* qkv_w   = (const float*)d_in[24];
    const float* proj_w  = (const float*)d_in[25];
    const float* bn_n4   = (const float*)d_in[26];
    const float* mlp1_w  = (const float*)d_in[27];
    const float* bn_mlp  = (const float*)d_in[28];
    const float* mlp2_w  = (const float*)d_in[29];
    const float* bn_n1   = (const float*)d_in[30];
    float* out = (float*)d_out;

    float* scr = nullptr;
    cudaGetSymbolAddress((void**)&scr, g_scr);
    float* x1o   = scr + O_X1O;
    float* t2    = scr + O_T2;
    float* tmp1  = scr + O_TMP1;
    float* bcdt0 = scr + O_BCDT0;
    float* hbuf  = scr + O_H;
    float* h2    = scr + O_H2;
    float* qkv   = scr + O_QKV;
    float* obuf  = scr + O_O;
    float* xa    = scr + O_XA;
    float* m1    = scr + O_M1;

    const long XBS = (long)ND * NL;
    const long C64 = (long)NC * NL;
    const long C128 = (long)NHID * NL;
    const long C192 = (long)192 * NL;
    const int PT = (NPAIRS + 127) / 128;

    static cudaStream_t s1 = nullptr, s2 = nullptr, s3 = nullptr;
    static cudaEvent_t eFork, eJ1, eJ2, eJ3;
    if (!s1) {
        cudaStreamCreateWithFlags(&s1, cudaStreamNonBlocking);
        cudaStreamCreateWithFlags(&s2, cudaStreamNonBlocking);
        cudaStreamCreateWithFlags(&s3, cudaStreamNonBlocking);
        cudaEventCreateWithFlags(&eFork, cudaEventDisableTiming);
        cudaEventCreateWithFlags(&eJ1, cudaEventDisableTiming);
        cudaEventCreateWithFlags(&eJ2, cudaEventDisableTiming);
        cudaEventCreateWithFlags(&eJ3, cudaEventDisableTiming);
        cudaFuncSetAttribute(ssd_Wh_k, cudaFuncAttributeMaxDynamicSharedMemorySize, SMEM_WH);
        cudaFuncSetAttribute(ssd_mix_k, cudaFuncAttributeMaxDynamicSharedMemorySize, SMEM_MIX);
        cudaFuncSetAttribute(ssd_out_k, cudaFuncAttributeMaxDynamicSharedMemorySize, SMEM_OUT);
    }

    cudaEventRecord(eFork, 0);
    cudaStreamWaitEvent(s1, eFork, 0);
    cudaStreamWaitEvent(s2, eFork, 0);
    cudaStreamWaitEvent(s3, eFork, 0);

    // ---- branch 2 (s1) ----
    mra_branch_k<<<NB * NC, 196, 0, s1>>>(x, hatt1_w, vatt1_w, hatt2_w, vatt2_w,
                                          bn_mra, xa);
    cudaEventRecord(eJ1, s1);

    // ---- branch 3 (s2): 4-node chain ----
    pwconv_k<64><<<dim3(192 / 16, PT), 128, 0, s2>>>(x + 128 * NL, XBS, bcdt_w, 192,
                                                     nullptr, nullptr, nullptr, 0,
                                                     bcdt0, C192, M_NONE);
    ssd_Wh_k<<<dim3(8, NB), 256, SMEM_WH, s2>>>(x, bcdt0, ssd_dw, A_param, hbuf);
    ssd_mix_k<<<NB, 256, SMEM_MIX, s2>>>(hbuf, hz_w, out_w, D_param, h2);
    ssd_out_k<<<dim3(4, 4, NB), 196, SMEM_OUT, s2>>>(h2, bcdt0, ssd_dw, xa);
    cudaEventRecord(eJ2, s2);

    // ---- branch 4 (s3) ----
    pwconv_k<64><<<dim3(192 / 16, PT), 128, 0, s3>>>(x + 192 * NL, XBS, qkv_w, 192,
                                                     nullptr, nullptr, nullptr, 0,
                                                     qkv, C192, M_NONE);
    attn_k<<<NB * NHEAD * 7, 128, 0, s3>>>(qkv, obuf);
    pwconv_k<64><<<dim3(NC / 16, PT), 128, 0, s3>>>(obuf, C64, proj_w, NC, nullptr,
                                                    bn_n4, x + 192 * NL, XBS,
                                                    xa + 192 * NL, XBS, M_ADD_BN);
    cudaEventRecord(eJ3, s3);

    // ---- branch 1 (default stream) ----
    dw7x7_k<<<NB * NC, 392>>>(x, XBS, dw1_w, dw1_b, bn_dw1, x1o, C64);
    star_k<<<dim3(NHID / 16, PT), 128>>>(x1o, f1_w, f1_b, f2_w, f2_b, t2);
    pwconv_k<128><<<dim3(NC / 16, PT), 128>>>(t2, C128, g_w, NC, g_b, bn_g,
                                              nullptr, 0, tmp1, C64, M_BN);
    dw7x7_k<<<NB * NC, 392>>>(tmp1, C64, dw2_w, dw2_b, nullptr, xa, XBS);

    // ---- join ----
    cudaStreamWaitEvent(0, eJ1, 0);
    cudaStreamWaitEvent(0, eJ2, 0);
    cudaStreamWaitEvent(0, eJ3, 0);

    // ---- merge MLP + residual ----
    pwconv_k<256><<<dim3(NHID / 16, PT), 128>>>(xa, XBS, mlp1_w, NHID, nullptr, bn_mlp,
                                                nullptr, 0, m1, C128, M_BN_RELU);
    pwconv_k<128><<<dim3(ND / 16, PT), 128>>>(m1, C128, mlp2_w, ND, nullptr, bn_n1,
                                              x, XBS, out, XBS, M_BN_ADD);
}

// round 7
// speedup vs baseline: 1.0789x; 1.0789x over previous
#include <cuda_runtime.h>
#include <math.h>

// ---------------- static config ----------------
static constexpr int NB = 8;
static constexpr int ND = 256;
static constexpr int NC = 64;
static constexpr int NHID = 128;
static constexpr int NS = 64;
static constexpr int NHH = 28, NWW = 28;
static constexpr int NL = NHH * NWW;      // 784
static constexpr int NHEAD = 16;
static constexpr int NPAIRS = NB * NL / 2;  // 3136
static constexpr int PPB = NL / 2;          // 392

// ---------------- scratch arena ----------------
static constexpr long O_X1O   = 0;                          // (8,64,784)
static constexpr long O_T2    = O_X1O   + (long)NB*NC*NL;   // (8,128,784)
static constexpr long O_TMP1  = O_T2    + (long)NB*NHID*NL; // (8,64,784)
static constexpr long O_BCDT0 = O_TMP1  + (long)NB*NC*NL;   // (8,192,784)
static constexpr long O_H     = O_BCDT0 + (long)NB*192*NL;  // (8,64,64)
static constexpr long O_H2    = O_H     + (long)NB*NC*NS;   // (8,64,64)
static constexpr long O_QKV   = O_H2    + (long)NB*NC*NS;   // (8,192,784)
static constexpr long O_O     = O_QKV   + (long)NB*192*NL;  // (8,64,784)
static constexpr long O_XA    = O_O     + (long)NB*NC*NL;   // (8,256,784)
static constexpr long O_M1    = O_XA    + (long)NB*ND*NL;   // (8,128,784)
static constexpr long SCR_TOTAL = O_M1 + (long)NB*NHID*NL;

__device__ __align__(16) float g_scr[SCR_TOTAL];

enum { M_NONE = 0, M_ADD_BN, M_BN_RELU, M_BN_ADD, M_BN };

// ---------------- pointwise conv, pixel-pair tiled ----------------
template <int CIN>
__global__ void pwconv_k(const float* __restrict__ in, long ibs,
                         const float* __restrict__ w, int cout,
                         const float* __restrict__ bias,
                         const float* __restrict__ bnp,
                         const float* __restrict__ res, long rbs,
                         float* __restrict__ out, long obs, int mode) {
    constexpr int OT = 16;
    __shared__ float ws[CIN * OT];
    int obase = blockIdx.x * OT;
    for (int idx = threadIdx.x; idx < CIN * OT; idx += 128) {
        int c = idx >> 4, i = idx & 15;
        ws[idx] = w[(long)(obase + i) * CIN + c];
    }
    __syncthreads();
    int pp = blockIdx.y * 128 + threadIdx.x;
    if (pp >= NPAIRS) return;
    int b = pp / PPB;
    int l = (pp % PPB) * 2;
    const float2* ip2 = reinterpret_cast<const float2*>(in + (long)b * ibs + l);

    float a0[OT], a1[OT];
#pragma unroll
    for (int i = 0; i < OT; i++) { a0[i] = 0.f; a1[i] = 0.f; }
#pragma unroll 4
    for (int c = 0; c < CIN; c++) {
        float2 xv = ip2[c * (NL / 2)];
        const float* wc = ws + c * OT;
#pragma unroll
        for (int i = 0; i < OT; i++) {
            float wv = wc[i];
            a0[i] += wv * xv.x;
            a1[i] += wv * xv.y;
        }
    }
#pragma unroll
    for (int i = 0; i < OT; i++) {
        int o = obase + i;
        float s0 = a0[i], s1 = a1[i];
        if (bias) { s0 += bias[o]; s1 += bias[o]; }
        if (mode >= M_ADD_BN) {
            long roff = (long)b * rbs + (long)o * NL + l;
            if (mode == M_ADD_BN) {
                float2 rv = *reinterpret_cast<const float2*>(res + roff);
                s0 += rv.x; s1 += rv.y;
            }
            float g = bnp[o], be = bnp[cout + o], mm = bnp[2 * cout + o], vv = bnp[3 * cout + o];
            float sc = g * rsqrtf(vv + 1e-5f);
            s0 = (s0 - mm) * sc + be;
            s1 = (s1 - mm) * sc + be;
            if (mode == M_BN_RELU) { s0 = fmaxf(s0, 0.f); s1 = fmaxf(s1, 0.f); }
            if (mode == M_BN_ADD) {
                float2 rv = *reinterpret_cast<const float2*>(res + roff);
                s0 += rv.x; s1 += rv.y;
            }
        }
        *reinterpret_cast<float2*>(out + (long)b * obs + (long)o * NL + l) =
            make_float2(s0, s1);
    }
}

// ---------------- fused star MLP ----------------
__global__ void star_k(const float* __restrict__ in,
                       const float* __restrict__ w1, const float* __restrict__ b1,
                       const float* __restrict__ w2, const float* __restrict__ b2,
                       float* __restrict__ out) {
    constexpr int OT = 16, CIN = NC;
    __shared__ float ws1[CIN * OT], ws2[CIN * OT];
    int obase = blockIdx.x * OT;
    for (int idx = threadIdx.x; idx < CIN * OT; idx += 128) {
        int c = idx >> 4, i = idx & 15;
        ws1[idx] = w1[(long)(obase + i) * CIN + c];
        ws2[idx] = w2[(long)(obase + i) * CIN + c];
    }
    __syncthreads();
    int pp = blockIdx.y * 128 + threadIdx.x;
    if (pp >= NPAIRS) return;
    int b = pp / PPB;
    int l = (pp % PPB) * 2;
    const float2* ip2 = reinterpret_cast<const float2*>(in + (long)b * NC * NL + l);

    float p0[OT], p1[OT], q0[OT], q1[OT];
#pragma unroll
    for (int i = 0; i < OT; i++) { p0[i] = p1[i] = q0[i] = q1[i] = 0.f; }
#pragma unroll 4
    for (int c = 0; c < CIN; c++) {
        float2 xv = ip2[c * (NL / 2)];
        const float* w1c = ws1 + c * OT;
        const float* w2c = ws2 + c * OT;
#pragma unroll
        for (int i = 0; i < OT; i++) {
            p0[i] += w1c[i] * xv.x; p1[i] += w1c[i] * xv.y;
            q0[i] += w2c[i] * xv.x; q1[i] += w2c[i] * xv.y;
        }
    }
#pragma unroll
    for (int i = 0; i < OT; i++) {
        int o = obase + i;
        float h0 = fminf(fmaxf(p0[i] + b1[o], 0.f), 6.f);
        float h1 = fminf(fmaxf(p1[i] + b1[o], 0.f), 6.f);
        float s0 = h0 * (q0[i] + b2[o]);
        float s1 = h1 * (q1[i] + b2[o]);
        *reinterpret_cast<float2*>(out + ((long)b * NHID + o) * NL + l) =
            make_float2(s0, s1);
    }
}

// ---------------- depthwise 7x7: 2 px/thread ----------------
__global__ void dw7x7_k(const float* __restrict__ in, long ibs,
                        const float* __restrict__ w, const float* __restrict__ bias,
                        const float* __restrict__ bnp,
                        float* __restrict__ out, long obs) {
    int bc = blockIdx.x;
    int c = bc % NC, b = bc / NC;
    const float* ip = in + (long)b * ibs + (long)c * NL;
    __shared__ float pl[34 * 34];
    __shared__ float wsh[49];
    int t = threadIdx.x;  // 392
    for (int i = t; i < 34 * 34; i += 392) pl[i] = 0.f;
    if (t < 49) wsh[t] = w[c * 49 + t];
    __syncthreads();
    {
        int l = t * 2;
        int y = l / NWW, x = l % NWW;
        float2 v = *reinterpret_cast<const float2*>(ip + l);
        pl[(y + 3) * 34 + x + 3] = v.x;
        pl[(y + 3) * 34 + x + 4] = v.y;
    }
    __syncthreads();
    float sc = 1.f, sh = 0.f;
    if (bnp) {
        float g = bnp[c], be = bnp[NC + c], mm = bnp[2 * NC + c], vv = bnp[3 * NC + c];
        sc = g * rsqrtf(vv + 1e-5f);
        sh = be - mm * sc;
    }
    float bi = bias[c];
    int y = t / 14, x0 = (t % 14) * 2;
    float s0 = 0.f, s1 = 0.f;
#pragma unroll
    for (int ky = 0; ky < 7; ky++) {
        float r[8];
        const float* row = pl + (y + ky) * 34 + x0;
#pragma unroll
        for (int kx = 0; kx < 8; kx++) r[kx] = row[kx];
#pragma unroll
        for (int kx = 0; kx < 7; kx++) {
            float wv = wsh[ky * 7 + kx];
            s0 += wv * r[kx];
            s1 += wv * r[kx + 1];
        }
    }
    s0 = (s0 + bi) * sc + sh;
    s1 = (s1 + bi) * sc + sh;
    *reinterpret_cast<float2*>(out + (long)b * obs + (long)c * NL + y * NWW + x0) =
        make_float2(s0, s1);
}

// ---------------- branch 2 fully fused ----------------
__global__ void mra_branch_k(const float* __restrict__ x,
                             const float* __restrict__ h1w, const float* __restrict__ v1w,
                             const float* __restrict__ h2w, const float* __restrict__ v2w,
                             const float* __restrict__ bnp, float* __restrict__ xa) {
    int bc = blockIdx.x;
    int c = bc % NC, b = bc / NC;
    const float* ip = x + ((long)b * ND + NC + c) * NL;
    __shared__ float xp[NL], mp[NL];
    __shared__ float xs[100], ht[190], vt[190], c2[190], c2v[190], att_s[100];
    int t = threadIdx.x;  // 196
    for (int i = t; i < NL; i += 196) xp[i] = ip[i];
    __syncthreads();
    for (int i = t; i < NL; i += 196) {
        int y = i / NWW, xx = i % NWW;
        float mx = -1e30f;
        for (int dy = -1; dy <= 1; dy++) {
            int yy = y + dy;
            if (yy < 0 || yy >= NHH) continue;
            for (int dx = -1; dx <= 1; dx++) {
                int xxx = xx + dx;
                if (xxx < 0 || xxx >= NWW) continue;
                mx = fmaxf(mx, xp[yy * NWW + xxx]);
            }
        }
        mp[i] = mx;
    }
    __syncthreads();
    if (t < 100) {
        int i = t / 10, j = t % 10;
        const float filt[4] = {1.f, 3.f, 3.f, 1.f};
        float s = 0.f;
        for (int fy = 0; fy < 4; fy++) {
            int oy = 3 * i + fy - 1;
            if (oy < 0) oy = -oy;
            if (oy >= NHH) oy = 2 * NHH - 2 - oy;
            for (int fx = 0; fx < 4; fx++) {
                int ox = 3 * j + fx - 1;
                if (ox < 0) ox = -ox;
                if (ox >= NWW) ox = 2 * NWW - 2 - ox;
                s += filt[fy] * filt[fx] * mp[oy * NWW + ox];
            }
        }
        xs[t] = s * (1.f / 64.f);
    }
    __syncthreads();
    if (t < 190) {
        {
            int row = t / 20, col = t % 20;
            ht[t] = (col < 10) ? xs[row * 10 + col] : 0.f;
        }
        {
            int a = t / 10, b2 = t % 10;
            int k = b2 * 19 + a, row = k / 20, col = k % 20;
            vt[t] = (col < 10) ? xs[col * 10 + row] : 0.f;
        }
    }
    __syncthreads();
    if (t < 190) {
        {
            int r = t / 19, j = t % 19;
            float s = 0.f;
            for (int ky = 0; ky < 11; ky++) {
                int yy = r + ky - 5;
                if (yy < 0 || yy >= 10) continue;
                for (int kx = 0; kx < 3; kx++) {
                    int xx = j + kx - 1;
                    if (xx < 0 || xx >= 19) continue;
                    s += h2w[c * 33 + ky * 3 + kx] * ht[yy * 19 + xx];
                }
            }
            c2[t] = s;
        }
        {
            int y = t / 10, x2 = t % 10;
            float s = 0.f;
            for (int ky = 0; ky < 3; ky++) {
                int yy = y + ky - 1;
                if (yy < 0 || yy >= 19) continue;
                for (int kx = 0; kx < 11; kx++) {
                    int xx = x2 + kx - 5;
                    if (xx < 0 || xx >= 10) continue;
                    s += v2w[c * 33 + ky * 11 + kx] * vt[yy * 10 + xx];
                }
            }
            c2v[t] = s;
        }
    }
    __syncthreads();
    if (t < 100) {
        int y = t / 10, xx = t % 10;
        float s = 0.f;
        for (int ky = 0; ky < 11; ky++) {
            int yy = y + ky - 5;
            if (yy < 0 || yy >= 10) continue;
            for (int kx = 0; kx < 3; kx++) {
                int xxx = xx + kx - 1;
                if (xxx < 0 || xxx >= 10) continue;
                s += h1w[c * 33 + ky * 3 + kx] * xs[yy * 10 + xxx];
            }
        }
        for (int ky = 0; ky < 3; ky++) {
            int yy = y + ky - 1;
            if (yy < 0 || yy >= 10) continue;
            for (int kx = 0; kx < 11; kx++) {
                int xxx = xx + kx - 5;
                if (xxx < 0 || xxx >= 10) continue;
                s += v1w[c * 33 + ky * 11 + kx] * xs[yy * 10 + xxx];
            }
        }
        s += c2[y * 20 + xx];
        int k4 = xx * 20 + y;
        s += c2v[(k4 % 19) * 10 + (k4 / 19)];
        float g = bnp[c], be = bnp[NC + c], mm = bnp[2 * NC + c], vv = bnp[3 * NC + c];
        float sc = g * rsqrtf(vv + 1e-5f);
        s = (s - mm) * sc + be;
        att_s[t] = 1.f / (1.f + __expf(-s));
    }
    __syncthreads();
    float* op = xa + (long)b * ND * NL + (long)(NC + c) * NL;
    for (int i = t; i < NL; i += 196) {
        int y = i / NWW, xx = i % NWW;
        int yo = (y * 10) / NHH, xo = (xx * 10) / NWW;
        op[i] = xp[i] * att_s[yo * 10 + xo];
    }
}

// ---------------- SSD fused: dw3x3(dt,Bm) + softmax + h-GEMM ----------------
__global__ void ssd_Wh_k(const float* __restrict__ x, const float* __restrict__ bcdt0,
                         const float* __restrict__ dw, const float* __restrict__ A_param,
                         float* __restrict__ h) {
    extern __shared__ float sm[];
    float* planes = sm;                 // 16 planes padded 30x30
    float* Wsh = sm + 16 * 900;         // 8 x 784
    int stile = blockIdx.x, b = blockIdx.y;
    int t = threadIdx.x;
    for (int i = t; i < 16 * 900; i += 256) planes[i] = 0.f;
    __syncthreads();
    for (int i = t; i < 16 * NL; i += 256) {
        int p = i / NL, l = i % NL;
        int ch = (p < 8) ? (stile * 8 + p) : (128 + stile * 8 + (p - 8));
        int y = l / NWW, xcol = l % NWW;
        planes[p * 900 + (y + 1) * 30 + xcol + 1] =
            bcdt0[((long)b * 192 + ch) * NL + l];
    }
    __syncthreads();
    int warp = t / 32, lane = t % 32;
    {
        int s = stile * 8 + warp;
        float wd[9], wb[9];
#pragma unroll
        for (int k = 0; k < 9; k++) {
            wd[k] = dw[(128 + s) * 9 + k];
            wb[k] = dw[s * 9 + k];
        }
        const float* dpl = planes + (8 + warp) * 900;
        const float* bpl = planes + warp * 900;
        float ap = A_param[s];
        float mx = -1e30f;
        for (int l = lane; l < NL; l += 32) {
            int y = l / NWW, xx = l % NWW;
            float v = 0.f;
#pragma unroll
            for (int ky = 0; ky < 3; ky++)
#pragma unroll
                for (int kx = 0; kx < 3; kx++)
                    v += wd[ky * 3 + kx] * dpl[(y + ky) * 30 + xx + kx];
            v += ap;
            Wsh[warp * NL + l] = v;
            mx = fmaxf(mx, v);
        }
#pragma unroll
        for (int o = 16; o > 0; o >>= 1) mx = fmaxf(mx, __shfl_xor_sync(0xffffffff, mx, o));
        float sum = 0.f;
        for (int l = lane; l < NL; l += 32) {
            float e = __expf(Wsh[warp * NL + l] - mx);
            Wsh[warp * NL + l] = e;
            sum += e;
        }
#pragma unroll
        for (int o = 16; o > 0; o >>= 1) sum += __shfl_xor_sync(0xffffffff, sum, o);
        float inv = 1.f / sum;
        for (int l = lane; l < NL; l += 32) {
            int y = l / NWW, xx = l % NWW;
            float v = 0.f;
#pragma unroll
            for (int ky = 0; ky < 3; ky++)
#pragma unroll
                for (int kx = 0; kx < 3; kx++)
                    v += wb[ky * 3 + kx] * bpl[(y + ky) * 30 + xx + kx];
            Wsh[warp * NL + l] *= inv * v;
        }
    }
    __syncthreads();
    for (int i = 0; i < 8; i++) {
        int c = i * 8 + warp;
        const float* xsrc = x + ((long)b * ND + 128 + c) * NL;
        float acc[8];
#pragma unroll
        for (int k = 0; k < 8; k++) acc[k] = 0.f;
        for (int l = lane; l < NL; l += 32) {
            float xv = xsrc[l];
#pragma unroll
            for (int k = 0; k < 8; k++) acc[k] += xv * Wsh[k * NL + l];
        }
#pragma unroll
        for (int k = 0; k < 8; k++) {
#pragma unroll
            for (int o = 16; o > 0; o >>= 1)
                acc[k] += __shfl_down_sync(0xffffffff, acc[k], o);
        }
        if (lane == 0) {
#pragma unroll
            for (int k = 0; k < 8; k++)
                h[((long)b * NC + c) * NS + stile * 8 + k] = acc[k];
        }
    }
}

// ---------------- SSD mix fused (hz + gate + out proj), register-blocked ----------------
// grid NB, 256 threads. Thread owns s = t&63, o-tile og = t>>6 (16 outputs).
// Weights staged TRANSPOSED (wt[c*64+o]) -> 16 weights via 4x LDS.128 broadcast.
__global__ void ssd_mix_k(const float* __restrict__ h, const float* __restrict__ hzw,
                          const float* __restrict__ ow, const float* __restrict__ D,
                          float* __restrict__ h2) {
    extern __shared__ float sm[];
    float* hs  = sm;             // 64x64 (h, [c][s])
    float* us  = sm + 4096;      // 64x64 (u, [c][s])
    float* wt1 = sm + 2 * 4096;  // transposed hz1: [c][o]
    float* wt2 = sm + 3 * 4096;  // transposed hz2: [c][o]
    int b = blockIdx.x, t = threadIdx.x;
    for (int i = t; i < NC * NS; i += 256) hs[i] = h[(long)b * NC * NS + i];
    for (int i = t; i < NC * NC; i += 256) {
        int c = i >> 6, o = i & 63;
        wt1[i] = hzw[o * NC + c];
        wt2[i] = hzw[(NC + o) * NC + c];
    }
    __syncthreads();
    float Dv = D[0];
    int s = t & 63, og = (t >> 6) << 4;  // 16-output tile base
    {
        float a1[16], a2[16];
#pragma unroll
        for (int i = 0; i < 16; i++) { a1[i] = 0.f; a2[i] = 0.f; }
        for (int c = 0; c < NC; c++) {
            float hv = hs[c * NS + s];
            const float4* w1p = reinterpret_cast<const float4*>(wt1 + c * NC + og);
            const float4* w2p = reinterpret_cast<const float4*>(wt2 + c * NC + og);
#pragma unroll
            for (int q = 0; q < 4; q++) {
                float4 w1v = w1p[q], w2v = w2p[q];
                a1[q * 4 + 0] += w1v.x * hv; a2[q * 4 + 0] += w2v.x * hv;
                a1[q * 4 + 1] += w1v.y * hv; a2[q * 4 + 1] += w2v.y * hv;
                a1[q * 4 + 2] += w1v.z * hv; a2[q * 4 + 2] += w2v.z * hv;
                a1[q * 4 + 3] += w1v.w * hv; a2[q * 4 + 3] += w2v.w * hv;
            }
        }
#pragma unroll
        for (int i = 0; i < 16; i++) {
            float sil = a2[i] / (1.f + __expf(-a2[i]));
            us[(og + i) * NS + s] = a1[i] * sil + a1[i] * Dv;
        }
    }
    __syncthreads();
    for (int i = t; i < NC * NC; i += 256) {
        int c = i >> 6, o = i & 63;
        wt1[i] = ow[o * NC + c];
    }
    __syncthreads();
    {
        float acc[16];
#pragma unroll
        for (int i = 0; i < 16; i++) acc[i] = 0.f;
        for (int c = 0; c < NC; c++) {
            float uv = us[c * NS + s];
            const float4* wp = reinterpret_cast<const float4*>(wt1 + c * NC + og);
#pragma unroll
            for (int q = 0; q < 4; q++) {
                float4 wv = wp[q];
                acc[q * 4 + 0] += wv.x * uv;
                acc[q * 4 + 1] += wv.y * uv;
                acc[q * 4 + 2] += wv.z * uv;
                acc[q * 4 + 3] += wv.w * uv;
            }
        }
#pragma unroll
        for (int i = 0; i < 16; i++)
            h2[(long)b * NC * NS + (og + i) * NS + s] = acc[i];
    }
}

// ---------------- SSD out: x3 = h2 @ conv3x3(Cm), inline conv ----------------
__global__ void ssd_out_k(const float* __restrict__ h2, const float* __restrict__ bcdt0,
                          const float* __restrict__ dw, float* __restrict__ xa) {
    extern __shared__ float sm[];
    float* inbuf = sm;             // 64 planes x 9 rows x 30 cols
    float* hst = sm + 64 * 270;    // 64 x 16 (transposed)
    float* wsh = hst + 1024;       // 64 x 9
    int cg = blockIdx.x, lt = blockIdx.y, b = blockIdx.z;
    int t = threadIdx.x;  // 196
    int r0 = lt * 7;
    for (int i = t; i < 64 * 270; i += 196) inbuf[i] = 0.f;
    for (int i = t; i < 64 * 9; i += 196) wsh[i] = dw[(64 + i / 9) * 9 + i % 9];
    for (int i = t; i < 16 * NS; i += 196) {
        int s = i / 16, ii = i % 16;
        hst[i] = h2[((long)b * NC + cg * 16 + ii) * NS + s];
    }
    __syncthreads();
    for (int i = t; i < 64 * 9 * 28; i += 196) {
        int s = i / 252, rem = i % 252;
        int rloc = rem / 28, col = rem % 28;
        int rr = r0 + rloc - 1;
        if (rr >= 0 && rr < NHH)
            inbuf[s * 270 + rloc * 30 + col + 1] =
                bcdt0[((long)b * 192 + 64 + s) * NL + rr * NWW + col];
    }
    __syncthreads();
    int l = lt * 196 + t;
    int ly = t / 28, xx = t % 28;
    float acc[16];
#pragma unroll
    for (int i = 0; i < 16; i++) acc[i] = 0.f;
    for (int s = 0; s < 64; s++) {
        const float* pb = inbuf + s * 270 + ly * 30 + xx;
        const float* wp = wsh + s * 9;
        float cv = 0.f;
#pragma unroll
        for (int ky = 0; ky < 3; ky++)
#pragma unroll
            for (int kx = 0; kx < 3; kx++)
                cv += wp[ky * 3 + kx] * pb[ky * 30 + kx];
        const float* hp = hst + s * 16;
#pragma unroll
        for (int i = 0; i < 16; i++) acc[i] += hp[i] * cv;
    }
#pragma unroll
    for (int i = 0; i < 16; i++)
        xa[(long)b * ND * NL + (long)(128 + cg * 16 + i) * NL + l] = acc[i];
}

// ---------------- GA attention ----------------
__global__ void attn_k(const float* __restrict__ qkv, float* __restrict__ o) {
    int blk = blockIdx.x;
    int rc = blk % 7;
    int bh = blk / 7;
    int head = bh % NHEAD, b = bh / NHEAD;
    __shared__ float Ks[NL * 4], Vs[NL * 4];
    const float* kbase = qkv + ((long)b * 192 + 64 + head * 4) * NL;
    const float* vbase = qkv + ((long)b * 192 + 128 + head * 4) * NL;
    for (int i = threadIdx.x; i < NL * 4; i += blockDim.x) {
        int d = i / NL, l = i % NL;
        Ks[l * 4 + d] = kbase[i];
        Vs[l * 4 + d] = vbase[i];
    }
    __syncthreads();
    int row = rc * 128 + threadIdx.x;
    if (row >= NL) return;
    const float* qb = qkv + ((long)b * 192 + head * 4) * NL;
    float q0 = qb[row] * 0.5f, q1 = qb[NL + row] * 0.5f;
    float q2 = qb[2 * NL + row] * 0.5f, q3 = qb[3 * NL + row] * 0.5f;
    float se = 0.f, a0 = 0.f, a1 = 0.f, a2 = 0.f, a3 = 0.f;
    const float4* K4 = reinterpret_cast<const float4*>(Ks);
    const float4* V4 = reinterpret_cast<const float4*>(Vs);
    for (int l = 0; l < NL; l++) {
        float4 kv = K4[l];
        float s = q0 * kv.x + q1 * kv.y + q2 * kv.z + q3 * kv.w;
        float p = __expf(s);
        float4 vv = V4[l];
        se += p;
        a0 += p * vv.x; a1 += p * vv.y; a2 += p * vv.z; a3 += p * vv.w;
    }
    float inv = 1.f / se;
    float* ob = o + ((long)b * NC + head * 4) * NL;
    ob[row] = a0 * inv;
    ob[NL + row] = a1 * inv;
    ob[2 * NL + row] = a2 * inv;
    ob[3 * NL + row] = a3 * inv;
}

// ---------------- launch ----------------
static constexpr int SMEM_WH  = (16 * 900 + 8 * NL) * 4;          // 82,688 B
static constexpr int SMEM_MIX = 4 * 4096 * 4;                     // 65,536 B
static constexpr int SMEM_OUT = (64 * 270 + 1024 + 576) * 4;      // 75,520 B

extern "C" void kernel_launch(void* const* d_in, const int* in_sizes, int n_in,
                              void* d_out, int out_size) {
    const float* x       = (const float*)d_in[0];
    const float* dw1_w   = (const float*)d_in[1];
    const float* dw1_b   = (const float*)d_in[2];
    const float* bn_dw1  = (const float*)d_in[3];
    const float* f1_w    = (const float*)d_in[4];
    const float* f1_b    = (const float*)d_in[5];
    const float* f2_w    = (const float*)d_in[6];
    const float* f2_b    = (const float*)d_in[7];
    const float* g_w     = (const float*)d_in[8];
    const float* g_b     = (const float*)d_in[9];
    const float* bn_g    = (const float*)d_in[10];
    const float* dw2_w   = (const float*)d_in[11];
    const float* dw2_b   = (const float*)d_in[12];
    const float* hatt1_w = (const float*)d_in[13];
    const float* vatt1_w = (const float*)d_in[14];
    const float* hatt2_w = (const float*)d_in[15];
    const float* vatt2_w = (const float*)d_in[16];
    const float* bn_mra  = (const float*)d_in[17];
    const float* bcdt_w  = (const float*)d_in[18];
    const float* ssd_dw  = (const float*)d_in[19];
    const float* hz_w    = (const float*)d_in[20];
    const float* out_w   = (const float*)d_in[21];
    const float* A_param = (const float*)d_in[22];
    const float* D_param = (const float*)d_in[23];
    const float* qkv_w   = (const float*)d_in[24];
    const float* proj_w  = (const float*)d_in[25];
    const float* bn_n4   = (const float*)d_in[26];
    const float* mlp1_w  = (const float*)d_in[27];
    const float* bn_mlp  = (const float*)d_in[28];
    const float* mlp2_w  = (const float*)d_in[29];
    const float* bn_n1   = (const float*)d_in[30];
    float* out = (float*)d_out;

    float* scr = nullptr;
    cudaGetSymbolAddress((void**)&scr, g_scr);
    float* x1o   = scr + O_X1O;
    float* t2    = scr + O_T2;
    float* tmp1  = scr + O_TMP1;
    float* bcdt0 = scr + O_BCDT0;
    float* hbuf  = scr + O_H;
    float* h2    = scr + O_H2;
    float* qkv   = scr + O_QKV;
    float* obuf  = scr + O_O;
    float* xa    = scr + O_XA;
    float* m1    = scr + O_M1;

    const long XBS = (long)ND * NL;
    const long C64 = (long)NC * NL;
    const long C128 = (long)NHID * NL;
    const long C192 = (long)192 * NL;
    const int PT = (NPAIRS + 127) / 128;

    static cudaStream_t s1 = nullptr, s2 = nullptr, s3 = nullptr;
    static cudaEvent_t eFork, eJ1, eJ2, eJ3;
    if (!s1) {
        cudaStreamCreateWithFlags(&s1, cudaStreamNonBlocking);
        cudaStreamCreateWithFlags(&s2, cudaStreamNonBlocking);
        cudaStreamCreateWithFlags(&s3, cudaStreamNonBlocking);
        cudaEventCreateWithFlags(&eFork, cudaEventDisableTiming);
        cudaEventCreateWithFlags(&eJ1, cudaEventDisableTiming);
        cudaEventCreateWithFlags(&eJ2, cudaEventDisableTiming);
        cudaEventCreateWithFlags(&eJ3, cudaEventDisableTiming);
        cudaFuncSetAttribute(ssd_Wh_k, cudaFuncAttributeMaxDynamicSharedMemorySize, SMEM_WH);
        cudaFuncSetAttribute(ssd_mix_k, cudaFuncAttributeMaxDynamicSharedMemorySize, SMEM_MIX);
        cudaFuncSetAttribute(ssd_out_k, cudaFuncAttributeMaxDynamicSharedMemorySize, SMEM_OUT);
    }

    cudaEventRecord(eFork, 0);
    cudaStreamWaitEvent(s1, eFork, 0);
    cudaStreamWaitEvent(s2, eFork, 0);
    cudaStreamWaitEvent(s3, eFork, 0);

    // ---- branch 2 (s1) ----
    mra_branch_k<<<NB * NC, 196, 0, s1>>>(x, hatt1_w, vatt1_w, hatt2_w, vatt2_w,
                                          bn_mra, xa);
    cudaEventRecord(eJ1, s1);

    // ---- branch 3 (s2): 4-node chain ----
    pwconv_k<64><<<dim3(192 / 16, PT), 128, 0, s2>>>(x + 128 * NL, XBS, bcdt_w, 192,
                                                     nullptr, nullptr, nullptr, 0,
                                                     bcdt0, C192, M_NONE);
    ssd_Wh_k<<<dim3(8, NB), 256, SMEM_WH, s2>>>(x, bcdt0, ssd_dw, A_param, hbuf);
    ssd_mix_k<<<NB, 256, SMEM_MIX, s2>>>(hbuf, hz_w, out_w, D_param, h2);
    ssd_out_k<<<dim3(4, 4, NB), 196, SMEM_OUT, s2>>>(h2, bcdt0, ssd_dw, xa);
    cudaEventRecord(eJ2, s2);

    // ---- branch 4 (s3) ----
    pwconv_k<64><<<dim3(192 / 16, PT), 128, 0, s3>>>(x + 192 * NL, XBS, qkv_w, 192,
                                                     nullptr, nullptr, nullptr, 0,
                                                     qkv, C192, M_NONE);
    attn_k<<<NB * NHEAD * 7, 128, 0, s3>>>(qkv, obuf);
    pwconv_k<64><<<dim3(NC / 16, PT), 128, 0, s3>>>(obuf, C64, proj_w, NC, nullptr,
                                                    bn_n4, x + 192 * NL, XBS,
                                                    xa + 192 * NL, XBS, M_ADD_BN);
    cudaEventRecord(eJ3, s3);

    // ---- branch 1 (default stream) ----
    dw7x7_k<<<NB * NC, 392>>>(x, XBS, dw1_w, dw1_b, bn_dw1, x1o, C64);
    star_k<<<dim3(NHID / 16, PT), 128>>>(x1o, f1_w, f1_b, f2_w, f2_b, t2);
    pwconv_k<128><<<dim3(NC / 16, PT), 128>>>(t2, C128, g_w, NC, g_b, bn_g,
                                              nullptr, 0, tmp1, C64, M_BN);
    dw7x7_k<<<NB * NC, 392>>>(tmp1, C64, dw2_w, dw2_b, nullptr, xa, XBS);

    // ---- join ----
    cudaStreamWaitEvent(0, eJ1, 0);
    cudaStreamWaitEvent(0, eJ2, 0);
    cudaStreamWaitEvent(0, eJ3, 0);

    // ---- merge MLP + residual ----
    pwconv_k<256><<<dim3(NHID / 16, PT), 128>>>(xa, XBS, mlp1_w, NHID, nullptr, bn_mlp,
                                                nullptr, 0, m1, C128, M_BN_RELU);
    pwconv_k<128><<<dim3(ND / 16, PT), 128>>>(m1, C128, mlp2_w, ND, nullptr, bn_n1,
                                              x, XBS, out, XBS, M_BN_ADD);
}